// round 7
// baseline (speedup 1.0000x reference)
#include <cuda_runtime.h>

#define N_NODES 50000
#define N_EDGES 800000
#define IN_DIM  96
#define HID     32
#define OUT_DIM 64

// ---------------- scratch (no allocations allowed) ----------------
__device__ float g_y1 [N_NODES * HID];   // x @ W1l
__device__ float g_z1 [N_NODES * HID];   // x @ W1r + b1
__device__ float g_agg[N_NODES * HID];   // accumulator: layer1, then reused for layer2
__device__ float g_h  [N_NODES * HID];   // relu output of layer 1
__device__ float g_cnt[N_NODES];         // in-degree (float)
__device__ int2  g_epack[N_EDGES];       // packed (src, dst) int32
__device__ int   g_is64;                 // 1 if edge_index buffer is int64

// Vector reduction: 16B atomic add (sm_90+, PTX ISA 8.1).
__device__ __forceinline__ void red_add_v4(float* addr, float4 v) {
    asm volatile("red.global.add.v4.f32 [%0], {%1, %2, %3, %4};"
                 :: "l"(addr), "f"(v.x), "f"(v.y), "f"(v.z), "f"(v.w)
                 : "memory");
}

// ---------------- kernels ----------------

// Zero accumulator + counts (float4). Thread 0 of block 0 also sniffs the
// edge_index dtype: little-endian int64 with values in [0, 50000) has every
// odd 32-bit word == 0; for int32 data the probed words are random endpoints
// and P(all 16 zero) ~ (2e-5)^16 ~ 0. Probes spread across the buffer.
__global__ void k_init(const int* __restrict__ ei32) {
    int i = blockIdx.x * blockDim.x + threadIdx.x;
    if (i == 0) {
        int is64 = 1;
        #pragma unroll
        for (int k = 0; k < 16; k++) {
            int idx = 2 * (k * 49999) + 1;   // max 1,499,971 < 1.6M ints (both dtypes)
            if (ei32[idx] != 0) is64 = 0;
        }
        g_is64 = is64;
    }
    int stride = gridDim.x * blockDim.x;
    float4 z = make_float4(0.f, 0.f, 0.f, 0.f);
    for (int j = i; j < N_NODES * HID / 4; j += stride)
        ((float4*)g_agg)[j] = z;
    for (int j = i; j < N_NODES; j += stride)
        g_cnt[j] = 0.0f;
}

// Normalize edge index to packed int32 pairs; count in-degrees.
__global__ void k_edges(const int* __restrict__ ei32) {
    int e = blockIdx.x * blockDim.x + threadIdx.x;
    if (e >= N_EDGES) return;
    int s, d;
    if (g_is64) {
        s = ei32[2 * e];                    // low word of int64
        d = ei32[2 * (N_EDGES + e)];
    } else {
        s = ei32[e];
        d = ei32[N_EDGES + e];
    }
    g_epack[e] = make_int2(s, d);
    atomicAdd(&g_cnt[d], 1.0f);
}

// Fused: y1 = x @ W1l ; z1 = x @ W1r + b1.  One warp per row, lane = out col.
__global__ __launch_bounds__(256) void k_lin1(const float* __restrict__ x,
                                              const float* __restrict__ W1l,
                                              const float* __restrict__ W1r,
                                              const float* __restrict__ b1) {
    __shared__ float sWl[IN_DIM * HID];
    __shared__ float sWr[IN_DIM * HID];
    __shared__ float sb [HID];
    __shared__ float sx [8][IN_DIM];

    int t = threadIdx.x;
    for (int i = t; i < IN_DIM * HID; i += 256) { sWl[i] = W1l[i]; sWr[i] = W1r[i]; }
    if (t < HID) sb[t] = b1[t];

    int w    = t >> 5;
    int lane = t & 31;
    int row  = blockIdx.x * 8 + w;
    if (row < N_NODES) {
        #pragma unroll
        for (int k = 0; k < IN_DIM / 32; k++)
            sx[w][lane + 32 * k] = x[row * IN_DIM + lane + 32 * k];
    }
    __syncthreads();
    if (row >= N_NODES) return;

    float a1 = 0.0f;
    float a2 = sb[lane];
    #pragma unroll
    for (int k = 0; k < IN_DIM; k++) {
        float xv = sx[w][k];
        a1 = fmaf(xv, sWl[k * HID + lane], a1);
        a2 = fmaf(xv, sWr[k * HID + lane], a2);
    }
    g_y1[row * HID + lane] = a1;
    g_z1[row * HID + lane] = a2;
}

// Scatter-add: 8 lanes per edge, each lane moves one float4 (16B).
// 4 edges per warp. LAYER=0: src g_y1, LAYER=1: src g_h.
template <int LAYER>
__global__ __launch_bounds__(256) void k_scatter() {
    int gtid = blockIdx.x * blockDim.x + threadIdx.x;
    int e    = gtid >> 3;          // edge index
    int sub  = gtid & 7;           // float4 chunk 0..7 (8*4 = 32 = HID)
    if (e >= N_EDGES) return;
    const int2* __restrict__ ep = g_epack;
    int2 sd = __ldg(&ep[e]);       // broadcast across the 8 lanes of this edge
    const float4* __restrict__ src =
        (const float4*)((LAYER == 0) ? g_y1 : g_h);
    float4 v = __ldg(&src[sd.x * (HID / 4) + sub]);
    red_add_v4(g_agg + sd.y * HID + sub * 4, v);
}

// h = relu(agg/max(cnt,1) + z1); re-zero agg for layer 2 in the same pass.
__global__ void k_relu() {
    int i = blockIdx.x * blockDim.x + threadIdx.x;  // float4 index
    if (i >= N_NODES * HID / 4) return;
    float c   = g_cnt[i >> 3];                       // 8 float4 per row
    float inv = 1.0f / fmaxf(c, 1.0f);
    float4 a  = ((float4*)g_agg)[i];
    float4 z  = ((float4*)g_z1)[i];
    float4 h;
    h.x = fmaxf(fmaf(a.x, inv, z.x), 0.0f);
    h.y = fmaxf(fmaf(a.y, inv, z.y), 0.0f);
    h.z = fmaxf(fmaf(a.z, inv, z.z), 0.0f);
    h.w = fmaxf(fmaf(a.w, inv, z.w), 0.0f);
    ((float4*)g_h)[i] = h;
    ((float4*)g_agg)[i] = make_float4(0.f, 0.f, 0.f, 0.f);
}

// out = (agg2/max(cnt,1)) @ W2l + h @ W2r + b2.  64 threads per row.
__global__ __launch_bounds__(256) void k_out(const float* __restrict__ W2l,
                                             const float* __restrict__ W2r,
                                             const float* __restrict__ b2,
                                             float* __restrict__ out) {
    __shared__ float sWl[HID * OUT_DIM];
    __shared__ float sWr[HID * OUT_DIM];
    __shared__ float sb [OUT_DIM];
    __shared__ float sa [4][HID];
    __shared__ float sh [4][HID];

    int t = threadIdx.x;
    for (int i = t; i < HID * OUT_DIM; i += 256) { sWl[i] = W2l[i]; sWr[i] = W2r[i]; }
    if (t < OUT_DIM) sb[t] = b2[t];

    int r   = t >> 6;        // 0..3 row within block
    int c   = t & 63;        // 0..63 out column
    int row = blockIdx.x * 4 + r;
    if (row < N_NODES) {
        if (c < HID) sa[r][c]       = g_agg[row * HID + c];
        else         sh[r][c - HID] = g_h [row * HID + (c - HID)];
    }
    __syncthreads();
    if (row >= N_NODES) return;

    float inv = 1.0f / fmaxf(g_cnt[row], 1.0f);
    float acc = sb[c];
    #pragma unroll
    for (int k = 0; k < HID; k++) {
        acc = fmaf(sa[r][k] * inv, sWl[k * OUT_DIM + c], acc);
        acc = fmaf(sh[r][k],       sWr[k * OUT_DIM + c], acc);
    }
    out[row * OUT_DIM + c] = acc;
}

// ---------------- launch ----------------
extern "C" void kernel_launch(void* const* d_in, const int* in_sizes, int n_in,
                              void* d_out, int out_size) {
    const float* x   = (const float*)d_in[0];
    const int*   ei  = (const int*)d_in[1];     // int32 view; dtype sniffed on device
    const float* W1l = (const float*)d_in[2];
    const float* W1r = (const float*)d_in[3];
    const float* b1  = (const float*)d_in[4];
    const float* W2l = (const float*)d_in[5];
    const float* W2r = (const float*)d_in[6];
    const float* b2  = (const float*)d_in[7];
    float*       out = (float*)d_out;

    k_init  <<<1024, 256>>>(ei);
    k_edges <<<(N_EDGES + 255) / 256, 256>>>(ei);
    k_lin1  <<<(N_NODES + 7) / 8, 256>>>(x, W1l, W1r, b1);
    k_scatter<0><<<(N_EDGES * 8 + 255) / 256, 256>>>();
    k_relu  <<<(N_NODES * HID / 4 + 255) / 256, 256>>>();
    k_scatter<1><<<(N_EDGES * 8 + 255) / 256, 256>>>();
    k_out   <<<(N_NODES + 3) / 4, 256>>>(W2l, W2r, b2, out);
}